// round 14
// baseline (speedup 1.0000x reference)
#include <cuda_runtime.h>
#include <cuda_fp16.h>
#include <math.h>
#include <stdint.h>

#define Dm 1024
#define DFF 4096
#define Bb 2048
#define NROW 73728
#define NQ 20480
#define OUTN ((size_t)6*2048*6*1024)

// ---------------- scratch ----------------
__device__ __half g_srch [(size_t)NROW*Dm];
__device__ __half g_kvh  [(size_t)NROW*2048];
__device__ __half g_qh   [(size_t)NQ*Dm];
__device__ __half g_ctxh [(size_t)NQ*Dm];
__device__ __half g_a1inh[(size_t)Bb*5120];
__device__ __half g_a2inh[(size_t)Bb*5120];
__device__ float  g_aggv [(size_t)Bb*Dm];
__device__ float  g_nagg [(size_t)Bb*Dm];
__device__ float  g_h1   [(size_t)Bb*5*Dm];
__device__ __half g_h1h  [(size_t)Bb*5*Dm];
__device__ __half g_r1h  [(size_t)Bb*5*DFF];
__device__ float  g_f1   [(size_t)Bb*5*Dm];
__device__ float  g_s1   [(size_t)Bb*Dm];
__device__ __half g_s1h  [(size_t)Bb*Dm];
__device__ __half g_r2h  [(size_t)Bb*DFF];
__device__ float  g_f2   [(size_t)Bb*Dm];
__device__ __half g_wh   [(size_t)31457280];
#define WIN  0
#define WOUT 3145728
#define A1W  4194304
#define A2W  9437184
#define F1W1 14680064
#define F1W2 18874368
#define F2W1 23068672
#define F2W2 27262976

__device__ __forceinline__ uint32_t smem_u32(const void* p) {
    uint32_t a;
    asm("{ .reg .u64 t; cvta.to.shared.u64 t, %1; cvt.u32.u64 %0, t; }" : "=r"(a) : "l"(p));
    return a;
}
__device__ __forceinline__ void cp16(uint32_t dst, const __half* src) {
    asm volatile("cp.async.cg.shared.global [%0], [%1], 16;"
                 :: "r"(dst), "l"(__cvta_generic_to_global(src)) : "memory");
}
#define CP_COMMIT() asm volatile("cp.async.commit_group;" ::: "memory")
#define CP_WAIT(n)  asm volatile("cp.async.wait_group %0;" :: "n"(n) : "memory")

__device__ __forceinline__ __half* scat_ptr(__half* a1, __half* a2, int i, int c) {
    if (i < 10240) return a1 + (long)(i & 2047)*5120 + (i >> 11)*1024 + c;
    int j = i - 10240;
    return a2 + (long)(j & 2047)*5120 + (j >> 11)*1024 + c;
}

// ---------------- f16 mma.sync GEMM, z-batched, opt gather / scatter ----------------
// CTA tile 128x128, BK=64, 256 thr (8 warps 2x4), warp tile 64x32.
// 3-stage cp.async, one barrier per K-step, rows padded to 144B. 2 CTA/SM.
// Fragment double-buffering: ldfrag(ks+1) overlaps mma(ks).
#define SMB 110592
template<int EPI, int OUT16, int GATHER, int SCAT>
__global__ void __launch_bounds__(256, 2) hgemm(
    int K,
    int N0, int M0, const __half* A0, const __half* W0, const float* b0, void* C0,
    int N1, int M1, const __half* A1, const __half* W1, const float* b1, void* C1,
    __half* sc1, __half* sc2)
{
    const __half* A; const __half* W; const float* bias; void* Cv; int M, N;
    const int z = blockIdx.z;
    if (z == 0) { A = A0; W = W0; bias = b0; Cv = C0; M = M0; N = N0; }
    else        { A = A1; W = W1; bias = b1; Cv = C1; M = M1; N = N1; }
    const long bm = (long)blockIdx.y * 128;
    const long bn = (long)blockIdx.x * 128;
    if (bm >= (long)M || bn >= (long)N) return;

    extern __shared__ char dsm[];
    const uint32_t base = smem_u32(dsm);
    const int tid = threadIdx.x;
    const int warp = tid >> 5, lane = tid & 31;
    const int wm = warp >> 2, wn = warp & 3;
    const int gr = lane >> 2, tg = lane & 3;

    float acc[4][4][4];
    #pragma unroll
    for (int i = 0; i < 4; i++)
        #pragma unroll
        for (int j = 0; j < 4; j++) {
            acc[i][j][0] = 0.f; acc[i][j][1] = 0.f;
            acc[i][j][2] = 0.f; acc[i][j][3] = 0.f;
        }

    const int S = K >> 6;
    auto stage = [&](int s, int b) {
        const int k0 = s << 6;
        #pragma unroll
        for (int i = 0; i < 4; i++) {
            int ch = tid + (i << 8);
            int r = ch >> 3, c = ch & 7;
            long rs;
            if (GATHER) {
                int gi = (int)bm + r;
                if (gi < 10240) { int sp = gi >> 11, b2 = gi & 2047; rs = ((long)(sp+1)*2048 + b2)*6; }
                else            { int j = gi - 10240; rs = (long)(j & 2047)*6 + (j >> 11) + 1; }
            } else rs = bm + r;
            cp16(base + (uint32_t)(b*36864 + r*144 + c*16),
                 A + rs*(long)K + k0 + c*8);
            cp16(base + (uint32_t)(b*36864 + 18432 + r*144 + c*16),
                 W + (bn + r)*(long)K + k0 + c*8);
        }
    };

    stage(0, 0); CP_COMMIT();
    stage(1, 1); CP_COMMIT();

    uint32_t af[2][4][4], bf[2][4][2];

    for (int s = 0; s < S; s++) {
        if (s + 1 < S) { CP_WAIT(1); } else { CP_WAIT(0); }
        __syncthreads();
        if (s + 2 < S) { stage(s + 2, (s + 2) % 3); CP_COMMIT(); }
        const uint32_t ab = base + (uint32_t)((s % 3) * 36864);
        const uint32_t bb = ab + 18432u;

        // fragment loader for sub-step ks into buffer pb
        auto ldfrag = [&](int ks, int pb) {
            #pragma unroll
            for (int mt = 0; mt < 4; mt++) {
                int row = wm*64 + mt*16 + (lane & 15);
                uint32_t p = ab + (uint32_t)(row*144 + (ks*2 + (lane >> 4))*16);
                asm volatile("ldmatrix.sync.aligned.m8n8.x4.shared.b16 {%0,%1,%2,%3}, [%4];"
                    : "=r"(af[pb][mt][0]), "=r"(af[pb][mt][1]),
                      "=r"(af[pb][mt][2]), "=r"(af[pb][mt][3])
                    : "r"(p));
            }
            #pragma unroll
            for (int np = 0; np < 2; np++) {
                int q = lane >> 3;
                int nrow = wn*32 + np*16 + (q >> 1)*8 + (lane & 7);
                uint32_t p = bb + (uint32_t)(nrow*144 + (ks*2 + (q & 1))*16);
                asm volatile("ldmatrix.sync.aligned.m8n8.x4.shared.b16 {%0,%1,%2,%3}, [%4];"
                    : "=r"(bf[pb][2*np][0]), "=r"(bf[pb][2*np][1]),
                      "=r"(bf[pb][2*np+1][0]), "=r"(bf[pb][2*np+1][1])
                    : "r"(p));
            }
        };

        ldfrag(0, 0);
        #pragma unroll
        for (int ks = 0; ks < 4; ks++) {
            const int pb = ks & 1;
            if (ks < 3) ldfrag(ks + 1, pb ^ 1);
            #pragma unroll
            for (int mt = 0; mt < 4; mt++)
                #pragma unroll
                for (int nt = 0; nt < 4; nt++) {
                    asm volatile(
                        "mma.sync.aligned.m16n8k16.row.col.f32.f16.f16.f32 "
                        "{%0,%1,%2,%3}, {%4,%5,%6,%7}, {%8,%9}, {%0,%1,%2,%3};"
                        : "+f"(acc[mt][nt][0]), "+f"(acc[mt][nt][1]),
                          "+f"(acc[mt][nt][2]), "+f"(acc[mt][nt][3])
                        : "r"(af[pb][mt][0]), "r"(af[pb][mt][1]),
                          "r"(af[pb][mt][2]), "r"(af[pb][mt][3]),
                          "r"(bf[pb][nt][0]), "r"(bf[pb][nt][1]));
                }
        }
    }

    // epilogue
    #pragma unroll
    for (int mt = 0; mt < 4; mt++) {
        long row0 = bm + wm*64 + mt*16 + gr;
        #pragma unroll
        for (int nt = 0; nt < 4; nt++) {
            int col0 = (int)bn + wn*32 + nt*8 + tg*2;
            float bv0 = __ldg(bias + col0);
            float bv1 = __ldg(bias + col0 + 1);
            float v00 = acc[mt][nt][0] + bv0;
            float v01 = acc[mt][nt][1] + bv1;
            float v10 = acc[mt][nt][2] + bv0;
            float v11 = acc[mt][nt][3] + bv1;
            if (EPI == 1) {
                v00 = fmaxf(v00, 0.f); v01 = fmaxf(v01, 0.f);
                v10 = fmaxf(v10, 0.f); v11 = fmaxf(v11, 0.f);
            }
            if (EPI == 2) {
                v00 = 1.f/(1.f+__expf(-v00)); v01 = 1.f/(1.f+__expf(-v01));
                v10 = 1.f/(1.f+__expf(-v10)); v11 = 1.f/(1.f+__expf(-v11));
            }
            if (SCAT) {
                *(__half2*)scat_ptr(sc1, sc2, (int)row0,     col0) = __floats2half2_rn(v00, v01);
                *(__half2*)scat_ptr(sc1, sc2, (int)row0 + 8, col0) = __floats2half2_rn(v10, v11);
            } else if (OUT16) {
                __half* C = (__half*)Cv;
                *(__half2*)(C + row0*(long)N + col0)     = __floats2half2_rn(v00, v01);
                *(__half2*)(C + (row0+8)*(long)N + col0) = __floats2half2_rn(v10, v11);
            } else {
                float* C = (float*)Cv;
                *(float2*)(C + row0*(long)N + col0)     = make_float2(v00, v01);
                *(float2*)(C + (row0+8)*(long)N + col0) = make_float2(v10, v11);
            }
        }
    }
}

// ---------------- weight convert ----------------
__global__ void k_cvtall(long base4, long n4,
                         const float4* s0, const float4* s1, const float4* s2,
                         const float4* s3, const float4* s4, const float4* s5,
                         const float4* s6, const float4* s7, uint2* d) {
    long i = base4 + (long)blockIdx.x * blockDim.x + threadIdx.x;
    if (i >= base4 + n4) return;
    const float4* s; long off;
    if      (i <  786432) { s = s0; off = 0; }
    else if (i < 1048576) { s = s1; off =  786432; }
    else if (i < 2359296) { s = s2; off = 1048576; }
    else if (i < 3670016) { s = s3; off = 2359296; }
    else if (i < 4718592) { s = s4; off = 3670016; }
    else if (i < 5767168) { s = s5; off = 4718592; }
    else if (i < 6815744) { s = s6; off = 5767168; }
    else                  { s = s7; off = 6815744; }
    float4 v = s[i - off];
    __half2 a = __floats2half2_rn(v.x, v.y), b = __floats2half2_rn(v.z, v.w);
    d[i] = make_uint2(*(uint32_t*)&a, *(uint32_t*)&b);
}

// ---------------- fused src-materialize + passthrough copy ----------------
__global__ void k_srcout(const float* __restrict__ F, const float* __restrict__ R,
                         __half* __restrict__ srch, float* __restrict__ out) {
    long i8 = (long)blockIdx.x * blockDim.x + threadIdx.x;
    long r = i8 >> 7; int d8 = (int)(i8 & 127);
    int l = (int)(r % 6); long sbq = r / 6;
    const float4* F4 = (const float4*)F;
    float4 v0 = F4[i8*2], v1 = F4[i8*2+1];
    if (r >= 12288) {
        ((float4*)out)[i8*2]   = v0;
        ((float4*)out)[i8*2+1] = v1;
    }
    if (l > 0) {
        const float4* R4 = (const float4*)R;
        long rb = (sbq*5 + (l-1))*256 + d8*2;
        float4 e0 = R4[rb], e1 = R4[rb+1];
        v0.x+=e0.x; v0.y+=e0.y; v0.z+=e0.z; v0.w+=e0.w;
        v1.x+=e1.x; v1.y+=e1.y; v1.z+=e1.z; v1.w+=e1.w;
    }
    __half2 h0=__floats2half2_rn(v0.x,v0.y), h1=__floats2half2_rn(v0.z,v0.w);
    __half2 h2=__floats2half2_rn(v1.x,v1.y), h3=__floats2half2_rn(v1.z,v1.w);
    ((uint4*)srch)[i8] = make_uint4(*(uint32_t*)&h0,*(uint32_t*)&h1,*(uint32_t*)&h2,*(uint32_t*)&h3);
}

// ---------------- attention (noun blocks remapped for KV locality) ----------------
__global__ void k_attn(const __half* __restrict__ q, const __half* __restrict__ kv,
                       __half* __restrict__ ctx) {
    int i = blockIdx.x, iq, seq;
    if (i < 10240) { int sp = i/2048, b = i%2048; seq = (sp+1)*2048 + b; iq = i; }
    else { int j = i - 10240; int b = j/5, m = j%5; seq = b; iq = 10240 + m*2048 + b; }
    const int warp = threadIdx.x >> 5, lane = threadIdx.x & 31;
    const __half* kb = kv + (long)seq * 12288;
    for (int h = warp; h < 16; h += 8) {
        float2 qf = __half22float2(*(const __half2*)(q + (long)iq*1024 + h*64 + lane*2));
        float sc[6];
        #pragma unroll
        for (int j = 0; j < 6; j++) {
            float2 kf = __half22float2(*(const __half2*)(kb + j*2048 + h*64 + lane*2));
            float p = qf.x*kf.x + qf.y*kf.y;
            #pragma unroll
            for (int o = 16; o; o >>= 1) p += __shfl_xor_sync(0xffffffffu, p, o);
            sc[j] = p * 0.125f;
        }
        float mx = sc[0];
        #pragma unroll
        for (int j = 1; j < 6; j++) mx = fmaxf(mx, sc[j]);
        float sum = 0.f;
        #pragma unroll
        for (int j = 0; j < 6; j++) { sc[j] = __expf(sc[j]-mx); sum += sc[j]; }
        float inv = 1.f/sum, o0 = 0.f, o1 = 0.f;
        #pragma unroll
        for (int j = 0; j < 6; j++) {
            float2 vf = __half22float2(*(const __half2*)(kb + j*2048 + 1024 + h*64 + lane*2));
            o0 = fmaf(sc[j]*inv, vf.x, o0); o1 = fmaf(sc[j]*inv, vf.y, o1);
        }
        *(__half2*)(ctx + (long)iq*1024 + h*64 + lane*2) = __floats2half2_rn(o0, o1);
    }
}

// ---------------- LayerNorm ----------------
__device__ __forceinline__ float bsum(float v) {
    __shared__ float sh[9];
    int lane = threadIdx.x & 31, w = threadIdx.x >> 5;
    #pragma unroll
    for (int o = 16; o; o >>= 1) v += __shfl_xor_sync(0xffffffffu, v, o);
    if (lane == 0) sh[w] = v;
    __syncthreads();
    if (w == 0) {
        float r = (lane < 8) ? sh[lane] : 0.f;
        #pragma unroll
        for (int o = 4; o; o >>= 1) r += __shfl_xor_sync(0xffffffffu, r, o);
        if (lane == 0) sh[8] = r;
    }
    __syncthreads();
    float out = sh[8];
    __syncthreads();
    return out;
}
__device__ __forceinline__ void ln_row(const float* pa, const float* pb,
                                       const float* g, const float* bv,
                                       float* po, __half* ph) {
    int tid = threadIdx.x;
    float v[4];
    #pragma unroll
    for (int t = 0; t < 4; t++) v[t] = pa[tid + t*256] + pb[tid + t*256];
    float mu = bsum(v[0]+v[1]+v[2]+v[3]) * (1.f/1024.f);
    float qv = 0.f;
    #pragma unroll
    for (int t = 0; t < 4; t++) { float d = v[t]-mu; qv += d*d; }
    float r = rsqrtf(bsum(qv) * (1.f/1024.f) + 1e-5f);
    #pragma unroll
    for (int t = 0; t < 4; t++) {
        int idx = tid + t*256;
        float o = (v[t]-mu)*r*g[idx] + bv[idx];
        po[idx] = o;
        if (ph) ph[idx] = __float2half_rn(o);
    }
}
__global__ void k_ln13(const float* F, const float* aggv, const float* nagg,
                       const float* g1, const float* b1v,
                       const float* g3, const float* b3v,
                       float* h1, __half* h1h, float* s1, __half* s1h) {
    int row = blockIdx.x;
    if (row < 10240) {
        int b = row/5, m = row%5;
        ln_row(F + ((long)b*6+1+m)*1024, aggv + (long)b*1024, g1, b1v,
               h1 + (long)row*1024, h1h + (long)row*1024);
    } else {
        int b = row - 10240;
        ln_row(F + (long)b*6144, nagg + (long)b*1024, g3, b3v,
               s1 + (long)b*1024, s1h + (long)b*1024);
    }
}
__global__ void k_ln24(const float* h1, const float* f1, const float* s1, const float* f2,
                       const float* g2, const float* b2v,
                       const float* g4, const float* b4v, float* out) {
    int row = blockIdx.x;
    if (row < 10240) {
        int b = row/5, m = row%5;
        ln_row(h1 + (long)row*1024, f1 + (long)row*1024, g2, b2v,
               out + ((long)b*6+1+m)*1024, (__half*)0);
    } else {
        int b = row - 10240;
        ln_row(s1 + (long)b*1024, f2 + (long)b*1024, g4, b4v,
               out + (long)b*6144, (__half*)0);
    }
}

// ---------------- host ----------------
template<typename T> static T* sym(const void* s) {
    void* p = nullptr; cudaGetSymbolAddress(&p, s); return (T*)p;
}

extern "C" void kernel_launch(void* const* d_in, const int* in_sizes, int n_in,
                              void* d_out, int out_size) {
    (void)in_sizes; (void)n_in; (void)out_size;
    const float *F=(const float*)d_in[0], *R=(const float*)d_in[1];
    const float *w_in=(const float*)d_in[2], *b_in=(const float*)d_in[3];
    const float *w_out=(const float*)d_in[4], *b_out=(const float*)d_in[5];
    const float *ln1g=(const float*)d_in[6], *ln1b=(const float*)d_in[7];
    const float *ln2g=(const float*)d_in[8], *ln2b=(const float*)d_in[9];
    const float *ln3g=(const float*)d_in[10], *ln3b=(const float*)d_in[11];
    const float *ln4g=(const float*)d_in[12], *ln4b=(const float*)d_in[13];
    const float *f1w1=(const float*)d_in[14], *f1b1=(const float*)d_in[15];
    const float *f1w2=(const float*)d_in[16], *f1b2=(const float*)d_in[17];
    const float *f2w1=(const float*)d_in[18], *f2b1=(const float*)d_in[19];
    const float *f2w2=(const float*)d_in[20], *f2b2=(const float*)d_in[21];
    const float *a1w=(const float*)d_in[22], *a1b=(const float*)d_in[23];
    const float *a2w=(const float*)d_in[24], *a2b=(const float*)d_in[25];
    float* out = (float*)d_out;

    __half *srch=sym<__half>(g_srch), *kvh=sym<__half>(g_kvh);
    __half *qh=sym<__half>(g_qh), *ctxh=sym<__half>(g_ctxh);
    __half *a1inh=sym<__half>(g_a1inh), *a2inh=sym<__half>(g_a2inh);
    float *aggv=sym<float>(g_aggv), *nagg=sym<float>(g_nagg);
    float *h1=sym<float>(g_h1), *f1=sym<float>(g_f1);
    float *s1=sym<float>(g_s1), *f2=sym<float>(g_f2);
    __half *h1h=sym<__half>(g_h1h), *r1h=sym<__half>(g_r1h);
    __half *s1h=sym<__half>(g_s1h), *r2h=sym<__half>(g_r2h);
    __half *wh=sym<__half>(g_wh);

    cudaFuncSetAttribute(hgemm<0,1,0,0>, cudaFuncAttributeMaxDynamicSharedMemorySize, SMB);
    cudaFuncSetAttribute(hgemm<0,1,1,0>, cudaFuncAttributeMaxDynamicSharedMemorySize, SMB);
    cudaFuncSetAttribute(hgemm<0,1,0,1>, cudaFuncAttributeMaxDynamicSharedMemorySize, SMB);
    cudaFuncSetAttribute(hgemm<0,0,0,0>, cudaFuncAttributeMaxDynamicSharedMemorySize, SMB);
    cudaFuncSetAttribute(hgemm<1,1,0,0>, cudaFuncAttributeMaxDynamicSharedMemorySize, SMB);
    cudaFuncSetAttribute(hgemm<2,0,0,0>, cudaFuncAttributeMaxDynamicSharedMemorySize, SMB);

    k_cvtall<<<15360, 256>>>(0, 3932160,
        (const float4*)w_in, (const float4*)w_out, (const float4*)a1w, (const float4*)a2w,
        (const float4*)f1w1, (const float4*)f1w2, (const float4*)f2w1, (const float4*)f2w2,
        (uint2*)wh);
    k_cvtall<<<15360, 256>>>(3932160, 3932160,
        (const float4*)w_in, (const float4*)w_out, (const float4*)a1w, (const float4*)a2w,
        (const float4*)f1w1, (const float4*)f1w2, (const float4*)f2w1, (const float4*)f2w2,
        (uint2*)wh);

    k_srcout<<<NROW/2, 256>>>(F, R, srch, out);

    // KV for all rows
    hgemm<0,1,0,0><<<dim3(16, NROW/128, 1), 256, SMB>>>(1024,
        2048, NROW, srch, wh+WIN+(size_t)1024*1024, b_in+1024, kvh,
        2048, NROW, srch, wh+WIN+(size_t)1024*1024, b_in+1024, kvh,
        (__half*)0, (__half*)0);
    // Q with fused gather
    hgemm<0,1,1,0><<<dim3(8, NQ/128, 1), 256, SMB>>>(1024,
        1024, NQ, srch, wh+WIN, b_in, qh,
        1024, NQ, srch, wh+WIN, b_in, qh,
        (__half*)0, (__half*)0);

    k_attn<<<NQ, 256>>>(qh, kvh, ctxh);

    // out projection with fused scatter
    hgemm<0,1,0,1><<<dim3(8, NQ/128, 1), 256, SMB>>>(1024,
        1024, NQ, ctxh, wh+WOUT, b_out, (void*)0,
        1024, NQ, ctxh, wh+WOUT, b_out, (void*)0,
        a1inh, a2inh);

    // batched agg gates
    hgemm<2,0,0,0><<<dim3(8, Bb/128, 2), 256, SMB>>>(5120,
        1024, Bb, a1inh, wh+A1W, a1b, aggv,
        1024, Bb, a2inh, wh+A2W, a2b, nagg,
        (__half*)0, (__half*)0);

    k_ln13<<<12288, 256>>>(F, aggv, nagg, ln1g, ln1b, ln3g, ln3b, h1, h1h, s1, s1h);

    hgemm<1,1,0,0><<<dim3(32, (Bb*5)/128, 2), 256, SMB>>>(1024,
        DFF, Bb*5, h1h, wh+F1W1, f1b1, r1h,
        DFF, Bb,   s1h, wh+F2W1, f2b1, r2h,
        (__half*)0, (__half*)0);
    hgemm<0,0,0,0><<<dim3(8, (Bb*5)/128, 2), 256, SMB>>>(DFF,
        1024, Bb*5, r1h, wh+F1W2, f1b2, f1,
        1024, Bb,   r2h, wh+F2W2, f2b2, f2,
        (__half*)0, (__half*)0);

    k_ln24<<<12288, 256>>>(h1, f1, s1, f2, ln2g, ln2b, ln4g, ln4b, out);
}

// round 15
// speedup vs baseline: 1.0026x; 1.0026x over previous
#include <cuda_runtime.h>
#include <cuda_fp16.h>
#include <math.h>
#include <stdint.h>

#define Dm 1024
#define DFF 4096
#define Bb 2048
#define NROW 73728
#define NQ 20480
#define OUTN ((size_t)6*2048*6*1024)

// ---------------- scratch ----------------
__device__ __half g_srch [(size_t)NROW*Dm];
__device__ __half g_kvh  [(size_t)NROW*2048];
__device__ __half g_qh   [(size_t)NQ*Dm];
__device__ __half g_ctxh [(size_t)NQ*Dm];
__device__ __half g_a1inh[(size_t)Bb*5120];
__device__ __half g_a2inh[(size_t)Bb*5120];
__device__ float  g_aggv [(size_t)Bb*Dm];
__device__ float  g_nagg [(size_t)Bb*Dm];
__device__ float  g_h1   [(size_t)Bb*5*Dm];
__device__ __half g_h1h  [(size_t)Bb*5*Dm];
__device__ __half g_r1h  [(size_t)Bb*5*DFF];
__device__ float  g_f1   [(size_t)Bb*5*Dm];
__device__ float  g_s1   [(size_t)Bb*Dm];
__device__ __half g_s1h  [(size_t)Bb*Dm];
__device__ __half g_r2h  [(size_t)Bb*DFF];
__device__ float  g_f2   [(size_t)Bb*Dm];
__device__ __half g_wh   [(size_t)31457280];
#define WIN  0
#define WOUT 3145728
#define A1W  4194304
#define A2W  9437184
#define F1W1 14680064
#define F1W2 18874368
#define F2W1 23068672
#define F2W2 27262976

__device__ __forceinline__ uint32_t smem_u32(const void* p) {
    uint32_t a;
    asm("{ .reg .u64 t; cvta.to.shared.u64 t, %1; cvt.u32.u64 %0, t; }" : "=r"(a) : "l"(p));
    return a;
}
__device__ __forceinline__ void cp16(uint32_t dst, const __half* src) {
    asm volatile("cp.async.cg.shared.global [%0], [%1], 16;"
                 :: "r"(dst), "l"(__cvta_generic_to_global(src)) : "memory");
}
#define CP_COMMIT() asm volatile("cp.async.commit_group;" ::: "memory")
#define CP_WAIT(n)  asm volatile("cp.async.wait_group %0;" :: "n"(n) : "memory")

__device__ __forceinline__ __half* scat_ptr(__half* a1, __half* a2, int i, int c) {
    if (i < 10240) return a1 + (long)(i & 2047)*5120 + (i >> 11)*1024 + c;
    int j = i - 10240;
    return a2 + (long)(j & 2047)*5120 + (j >> 11)*1024 + c;
}

// ---------------- f16 mma.sync GEMM, z-batched, opt gather / scatter ----------------
// CTA tile 128x128, BK=64, 256 thr (8 warps 2x4), warp tile 64x32.
// 3-stage cp.async, one barrier per K-step, rows padded to 144B. 2 CTA/SM.
#define SMB 110592
template<int EPI, int OUT16, int GATHER, int SCAT>
__global__ void __launch_bounds__(256, 2) hgemm(
    int K,
    int N0, int M0, const __half* A0, const __half* W0, const float* b0, void* C0,
    int N1, int M1, const __half* A1, const __half* W1, const float* b1, void* C1,
    __half* sc1, __half* sc2)
{
    const __half* A; const __half* W; const float* bias; void* Cv; int M, N;
    const int z = blockIdx.z;
    if (z == 0) { A = A0; W = W0; bias = b0; Cv = C0; M = M0; N = N0; }
    else        { A = A1; W = W1; bias = b1; Cv = C1; M = M1; N = N1; }
    const long bm = (long)blockIdx.y * 128;
    const long bn = (long)blockIdx.x * 128;
    if (bm >= (long)M || bn >= (long)N) return;

    extern __shared__ char dsm[];
    const uint32_t base = smem_u32(dsm);
    const int tid = threadIdx.x;
    const int warp = tid >> 5, lane = tid & 31;
    const int wm = warp >> 2, wn = warp & 3;
    const int gr = lane >> 2, tg = lane & 3;

    float acc[4][4][4];
    #pragma unroll
    for (int i = 0; i < 4; i++)
        #pragma unroll
        for (int j = 0; j < 4; j++) {
            acc[i][j][0] = 0.f; acc[i][j][1] = 0.f;
            acc[i][j][2] = 0.f; acc[i][j][3] = 0.f;
        }

    const int S = K >> 6;
    auto stage = [&](int s, int b) {
        const int k0 = s << 6;
        #pragma unroll
        for (int i = 0; i < 4; i++) {
            int ch = tid + (i << 8);
            int r = ch >> 3, c = ch & 7;
            long rs;
            if (GATHER) {
                int gi = (int)bm + r;
                if (gi < 10240) { int sp = gi >> 11, b2 = gi & 2047; rs = ((long)(sp+1)*2048 + b2)*6; }
                else            { int j = gi - 10240; rs = (long)(j & 2047)*6 + (j >> 11) + 1; }
            } else rs = bm + r;
            cp16(base + (uint32_t)(b*36864 + r*144 + c*16),
                 A + rs*(long)K + k0 + c*8);
            cp16(base + (uint32_t)(b*36864 + 18432 + r*144 + c*16),
                 W + (bn + r)*(long)K + k0 + c*8);
        }
    };

    stage(0, 0); CP_COMMIT();
    stage(1, 1); CP_COMMIT();

    for (int s = 0; s < S; s++) {
        if (s + 1 < S) { CP_WAIT(1); } else { CP_WAIT(0); }
        __syncthreads();
        if (s + 2 < S) { stage(s + 2, (s + 2) % 3); CP_COMMIT(); }
        const uint32_t ab = base + (uint32_t)((s % 3) * 36864);
        const uint32_t bb = ab + 18432u;

        #pragma unroll
        for (int ks = 0; ks < 4; ks++) {
            uint32_t af[4][4], bf[4][2];
            #pragma unroll
            for (int mt = 0; mt < 4; mt++) {
                int row = wm*64 + mt*16 + (lane & 15);
                uint32_t p = ab + (uint32_t)(row*144 + (ks*2 + (lane >> 4))*16);
                asm volatile("ldmatrix.sync.aligned.m8n8.x4.shared.b16 {%0,%1,%2,%3}, [%4];"
                    : "=r"(af[mt][0]), "=r"(af[mt][1]), "=r"(af[mt][2]), "=r"(af[mt][3])
                    : "r"(p));
            }
            #pragma unroll
            for (int np = 0; np < 2; np++) {
                int q = lane >> 3;
                int nrow = wn*32 + np*16 + (q >> 1)*8 + (lane & 7);
                uint32_t p = bb + (uint32_t)(nrow*144 + (ks*2 + (q & 1))*16);
                asm volatile("ldmatrix.sync.aligned.m8n8.x4.shared.b16 {%0,%1,%2,%3}, [%4];"
                    : "=r"(bf[2*np][0]), "=r"(bf[2*np][1]),
                      "=r"(bf[2*np+1][0]), "=r"(bf[2*np+1][1])
                    : "r"(p));
            }
            #pragma unroll
            for (int mt = 0; mt < 4; mt++)
                #pragma unroll
                for (int nt = 0; nt < 4; nt++) {
                    asm volatile(
                        "mma.sync.aligned.m16n8k16.row.col.f32.f16.f16.f32 "
                        "{%0,%1,%2,%3}, {%4,%5,%6,%7}, {%8,%9}, {%0,%1,%2,%3};"
                        : "+f"(acc[mt][nt][0]), "+f"(acc[mt][nt][1]),
                          "+f"(acc[mt][nt][2]), "+f"(acc[mt][nt][3])
                        : "r"(af[mt][0]), "r"(af[mt][1]), "r"(af[mt][2]), "r"(af[mt][3]),
                          "r"(bf[nt][0]), "r"(bf[nt][1]));
                }
        }
    }

    // epilogue
    #pragma unroll
    for (int mt = 0; mt < 4; mt++) {
        long row0 = bm + wm*64 + mt*16 + gr;
        #pragma unroll
        for (int nt = 0; nt < 4; nt++) {
            int col0 = (int)bn + wn*32 + nt*8 + tg*2;
            float bv0 = __ldg(bias + col0);
            float bv1 = __ldg(bias + col0 + 1);
            float v00 = acc[mt][nt][0] + bv0;
            float v01 = acc[mt][nt][1] + bv1;
            float v10 = acc[mt][nt][2] + bv0;
            float v11 = acc[mt][nt][3] + bv1;
            if (EPI == 1) {
                v00 = fmaxf(v00, 0.f); v01 = fmaxf(v01, 0.f);
                v10 = fmaxf(v10, 0.f); v11 = fmaxf(v11, 0.f);
            }
            if (EPI == 2) {
                v00 = 1.f/(1.f+__expf(-v00)); v01 = 1.f/(1.f+__expf(-v01));
                v10 = 1.f/(1.f+__expf(-v10)); v11 = 1.f/(1.f+__expf(-v11));
            }
            if (SCAT) {
                *(__half2*)scat_ptr(sc1, sc2, (int)row0,     col0) = __floats2half2_rn(v00, v01);
                *(__half2*)scat_ptr(sc1, sc2, (int)row0 + 8, col0) = __floats2half2_rn(v10, v11);
            } else if (OUT16) {
                __half* C = (__half*)Cv;
                *(__half2*)(C + row0*(long)N + col0)     = __floats2half2_rn(v00, v01);
                *(__half2*)(C + (row0+8)*(long)N + col0) = __floats2half2_rn(v10, v11);
            } else {
                float* C = (float*)Cv;
                *(float2*)(C + row0*(long)N + col0)     = make_float2(v00, v01);
                *(float2*)(C + (row0+8)*(long)N + col0) = make_float2(v10, v11);
            }
        }
    }
}

// ---------------- merged prep: srcout (blocks 0..36863) + weight cvt (36864..67583) ----------------
__global__ void k_prep(const float* __restrict__ F, const float* __restrict__ R,
                       __half* __restrict__ srch, float* __restrict__ out,
                       const float4* s0, const float4* s1, const float4* s2,
                       const float4* s3, const float4* s4, const float4* s5,
                       const float4* s6, const float4* s7, uint2* d) {
    if (blockIdx.x < 36864) {
        // src materialization + passthrough copy of slices 1..5
        long i8 = (long)blockIdx.x * blockDim.x + threadIdx.x;
        long r = i8 >> 7; int d8 = (int)(i8 & 127);
        int l = (int)(r % 6); long sbq = r / 6;
        const float4* F4 = (const float4*)F;
        float4 v0 = F4[i8*2], v1 = F4[i8*2+1];
        if (r >= 12288) {
            ((float4*)out)[i8*2]   = v0;
            ((float4*)out)[i8*2+1] = v1;
        }
        if (l > 0) {
            const float4* R4 = (const float4*)R;
            long rb = (sbq*5 + (l-1))*256 + d8*2;
            float4 e0 = R4[rb], e1 = R4[rb+1];
            v0.x+=e0.x; v0.y+=e0.y; v0.z+=e0.z; v0.w+=e0.w;
            v1.x+=e1.x; v1.y+=e1.y; v1.z+=e1.z; v1.w+=e1.w;
        }
        __half2 h0=__floats2half2_rn(v0.x,v0.y), h1=__floats2half2_rn(v0.z,v0.w);
        __half2 h2=__floats2half2_rn(v1.x,v1.y), h3=__floats2half2_rn(v1.z,v1.w);
        ((uint4*)srch)[i8] = make_uint4(*(uint32_t*)&h0,*(uint32_t*)&h1,*(uint32_t*)&h2,*(uint32_t*)&h3);
    } else {
        // weight f32 -> f16 into contiguous g_wh
        long i = (long)(blockIdx.x - 36864) * blockDim.x + threadIdx.x;
        if (i >= 7864320) return;
        const float4* s; long off;
        if      (i <  786432) { s = s0; off = 0; }
        else if (i < 1048576) { s = s1; off =  786432; }
        else if (i < 2359296) { s = s2; off = 1048576; }
        else if (i < 3670016) { s = s3; off = 2359296; }
        else if (i < 4718592) { s = s4; off = 3670016; }
        else if (i < 5767168) { s = s5; off = 4718592; }
        else if (i < 6815744) { s = s6; off = 5767168; }
        else                  { s = s7; off = 6815744; }
        float4 v = s[i - off];
        __half2 a = __floats2half2_rn(v.x, v.y), b = __floats2half2_rn(v.z, v.w);
        d[i] = make_uint2(*(uint32_t*)&a, *(uint32_t*)&b);
    }
}

// ---------------- attention (noun blocks remapped for KV locality) ----------------
__global__ void k_attn(const __half* __restrict__ q, const __half* __restrict__ kv,
                       __half* __restrict__ ctx) {
    int i = blockIdx.x, iq, seq;
    if (i < 10240) { int sp = i/2048, b = i%2048; seq = (sp+1)*2048 + b; iq = i; }
    else { int j = i - 10240; int b = j/5, m = j%5; seq = b; iq = 10240 + m*2048 + b; }
    const int warp = threadIdx.x >> 5, lane = threadIdx.x & 31;
    const __half* kb = kv + (long)seq * 12288;
    for (int h = warp; h < 16; h += 8) {
        float2 qf = __half22float2(*(const __half2*)(q + (long)iq*1024 + h*64 + lane*2));
        float sc[6];
        #pragma unroll
        for (int j = 0; j < 6; j++) {
            float2 kf = __half22float2(*(const __half2*)(kb + j*2048 + h*64 + lane*2));
            float p = qf.x*kf.x + qf.y*kf.y;
            #pragma unroll
            for (int o = 16; o; o >>= 1) p += __shfl_xor_sync(0xffffffffu, p, o);
            sc[j] = p * 0.125f;
        }
        float mx = sc[0];
        #pragma unroll
        for (int j = 1; j < 6; j++) mx = fmaxf(mx, sc[j]);
        float sum = 0.f;
        #pragma unroll
        for (int j = 0; j < 6; j++) { sc[j] = __expf(sc[j]-mx); sum += sc[j]; }
        float inv = 1.f/sum, o0 = 0.f, o1 = 0.f;
        #pragma unroll
        for (int j = 0; j < 6; j++) {
            float2 vf = __half22float2(*(const __half2*)(kb + j*2048 + 1024 + h*64 + lane*2));
            o0 = fmaf(sc[j]*inv, vf.x, o0); o1 = fmaf(sc[j]*inv, vf.y, o1);
        }
        *(__half2*)(ctx + (long)iq*1024 + h*64 + lane*2) = __floats2half2_rn(o0, o1);
    }
}

// ---------------- LayerNorm ----------------
__device__ __forceinline__ float bsum(float v) {
    __shared__ float sh[9];
    int lane = threadIdx.x & 31, w = threadIdx.x >> 5;
    #pragma unroll
    for (int o = 16; o; o >>= 1) v += __shfl_xor_sync(0xffffffffu, v, o);
    if (lane == 0) sh[w] = v;
    __syncthreads();
    if (w == 0) {
        float r = (lane < 8) ? sh[lane] : 0.f;
        #pragma unroll
        for (int o = 4; o; o >>= 1) r += __shfl_xor_sync(0xffffffffu, r, o);
        if (lane == 0) sh[8] = r;
    }
    __syncthreads();
    float out = sh[8];
    __syncthreads();
    return out;
}
__device__ __forceinline__ void ln_row(const float* pa, const float* pb,
                                       const float* g, const float* bv,
                                       float* po, __half* ph) {
    int tid = threadIdx.x;
    float v[4];
    #pragma unroll
    for (int t = 0; t < 4; t++) v[t] = pa[tid + t*256] + pb[tid + t*256];
    float mu = bsum(v[0]+v[1]+v[2]+v[3]) * (1.f/1024.f);
    float qv = 0.f;
    #pragma unroll
    for (int t = 0; t < 4; t++) { float d = v[t]-mu; qv += d*d; }
    float r = rsqrtf(bsum(qv) * (1.f/1024.f) + 1e-5f);
    #pragma unroll
    for (int t = 0; t < 4; t++) {
        int idx = tid + t*256;
        float o = (v[t]-mu)*r*g[idx] + bv[idx];
        po[idx] = o;
        if (ph) ph[idx] = __float2half_rn(o);
    }
}
__global__ void k_ln13(const float* F, const float* aggv, const float* nagg,
                       const float* g1, const float* b1v,
                       const float* g3, const float* b3v,
                       float* h1, __half* h1h, float* s1, __half* s1h) {
    int row = blockIdx.x;
    if (row < 10240) {
        int b = row/5, m = row%5;
        ln_row(F + ((long)b*6+1+m)*1024, aggv + (long)b*1024, g1, b1v,
               h1 + (long)row*1024, h1h + (long)row*1024);
    } else {
        int b = row - 10240;
        ln_row(F + (long)b*6144, nagg + (long)b*1024, g3, b3v,
               s1 + (long)b*1024, s1h + (long)b*1024);
    }
}
__global__ void k_ln24(const float* h1, const float* f1, const float* s1, const float* f2,
                       const float* g2, const float* b2v,
                       const float* g4, const float* b4v, float* out) {
    int row = blockIdx.x;
    if (row < 10240) {
        int b = row/5, m = row%5;
        ln_row(h1 + (long)row*1024, f1 + (long)row*1024, g2, b2v,
               out + ((long)b*6+1+m)*1024, (__half*)0);
    } else {
        int b = row - 10240;
        ln_row(s1 + (long)b*1024, f2 + (long)b*1024, g4, b4v,
               out + (long)b*6144, (__half*)0);
    }
}

// ---------------- host ----------------
template<typename T> static T* sym(const void* s) {
    void* p = nullptr; cudaGetSymbolAddress(&p, s); return (T*)p;
}

extern "C" void kernel_launch(void* const* d_in, const int* in_sizes, int n_in,
                              void* d_out, int out_size) {
    (void)in_sizes; (void)n_in; (void)out_size;
    const float *F=(const float*)d_in[0], *R=(const float*)d_in[1];
    const float *w_in=(const float*)d_in[2], *b_in=(const float*)d_in[3];
    const float *w_out=(const float*)d_in[4], *b_out=(const float*)d_in[5];
    const float *ln1g=(const float*)d_in[6], *ln1b=(const float*)d_in[7];
    const float *ln2g=(const float*)d_in[8], *ln2b=(const float*)d_in[9];
    const float *ln3g=(const float*)d_in[10], *ln3b=(const float*)d_in[11];
    const float *ln4g=(const float*)d_in[12], *ln4b=(const float*)d_in[13];
    const float *f1w1=(const float*)d_in[14], *f1b1=(const float*)d_in[15];
    const float *f1w2=(const float*)d_in[16], *f1b2=(const float*)d_in[17];
    const float *f2w1=(const float*)d_in[18], *f2b1=(const float*)d_in[19];
    const float *f2w2=(const float*)d_in[20], *f2b2=(const float*)d_in[21];
    const float *a1w=(const float*)d_in[22], *a1b=(const float*)d_in[23];
    const float *a2w=(const float*)d_in[24], *a2b=(const float*)d_in[25];
    float* out = (float*)d_out;

    __half *srch=sym<__half>(g_srch), *kvh=sym<__half>(g_kvh);
    __half *qh=sym<__half>(g_qh), *ctxh=sym<__half>(g_ctxh);
    __half *a1inh=sym<__half>(g_a1inh), *a2inh=sym<__half>(g_a2inh);
    float *aggv=sym<float>(g_aggv), *nagg=sym<float>(g_nagg);
    float *h1=sym<float>(g_h1), *f1=sym<float>(g_f1);
    float *s1=sym<float>(g_s1), *f2=sym<float>(g_f2);
    __half *h1h=sym<__half>(g_h1h), *r1h=sym<__half>(g_r1h);
    __half *s1h=sym<__half>(g_s1h), *r2h=sym<__half>(g_r2h);
    __half *wh=sym<__half>(g_wh);

    cudaFuncSetAttribute(hgemm<0,1,0,0>, cudaFuncAttributeMaxDynamicSharedMemorySize, SMB);
    cudaFuncSetAttribute(hgemm<0,1,1,0>, cudaFuncAttributeMaxDynamicSharedMemorySize, SMB);
    cudaFuncSetAttribute(hgemm<0,1,0,1>, cudaFuncAttributeMaxDynamicSharedMemorySize, SMB);
    cudaFuncSetAttribute(hgemm<0,0,0,0>, cudaFuncAttributeMaxDynamicSharedMemorySize, SMB);
    cudaFuncSetAttribute(hgemm<1,1,0,0>, cudaFuncAttributeMaxDynamicSharedMemorySize, SMB);
    cudaFuncSetAttribute(hgemm<2,0,0,0>, cudaFuncAttributeMaxDynamicSharedMemorySize, SMB);

    // merged src-materialize + passthrough + weight convert (one launch)
    k_prep<<<67584, 256>>>(F, R, srch, out,
        (const float4*)w_in, (const float4*)w_out, (const float4*)a1w, (const float4*)a2w,
        (const float4*)f1w1, (const float4*)f1w2, (const float4*)f2w1, (const float4*)f2w2,
        (uint2*)wh);

    // KV for all rows
    hgemm<0,1,0,0><<<dim3(16, NROW/128, 1), 256, SMB>>>(1024,
        2048, NROW, srch, wh+WIN+(size_t)1024*1024, b_in+1024, kvh,
        2048, NROW, srch, wh+WIN+(size_t)1024*1024, b_in+1024, kvh,
        (__half*)0, (__half*)0);
    // Q with fused gather
    hgemm<0,1,1,0><<<dim3(8, NQ/128, 1), 256, SMB>>>(1024,
        1024, NQ, srch, wh+WIN, b_in, qh,
        1024, NQ, srch, wh+WIN, b_in, qh,
        (__half*)0, (__half*)0);

    k_attn<<<NQ, 256>>>(qh, kvh, ctxh);

    // out projection with fused scatter
    hgemm<0,1,0,1><<<dim3(8, NQ/128, 1), 256, SMB>>>(1024,
        1024, NQ, ctxh, wh+WOUT, b_out, (void*)0,
        1024, NQ, ctxh, wh+WOUT, b_out, (void*)0,
        a1inh, a2inh);

    // batched agg gates
    hgemm<2,0,0,0><<<dim3(8, Bb/128, 2), 256, SMB>>>(5120,
        1024, Bb, a1inh, wh+A1W, a1b, aggv,
        1024, Bb, a2inh, wh+A2W, a2b, nagg,
        (__half*)0, (__half*)0);

    k_ln13<<<12288, 256>>>(F, aggv, nagg, ln1g, ln1b, ln3g, ln3b, h1, h1h, s1, s1h);

    hgemm<1,1,0,0><<<dim3(32, (Bb*5)/128, 2), 256, SMB>>>(1024,
        DFF, Bb*5, h1h, wh+F1W1, f1b1, r1h,
        DFF, Bb,   s1h, wh+F2W1, f2b1, r2h,
        (__half*)0, (__half*)0);
    hgemm<0,0,0,0><<<dim3(8, (Bb*5)/128, 2), 256, SMB>>>(DFF,
        1024, Bb*5, r1h, wh+F1W2, f1b2, f1,
        1024, Bb,   r2h, wh+F2W2, f2b2, f2,
        (__half*)0, (__half*)0);

    k_ln24<<<12288, 256>>>(h1, f1, s1, f2, ln2g, ln2b, ln4g, ln4b, out);
}

// round 16
// speedup vs baseline: 1.0177x; 1.0151x over previous
#include <cuda_runtime.h>
#include <cuda_fp16.h>
#include <math.h>
#include <stdint.h>

#define Dm 1024
#define DFF 4096
#define Bb 2048
#define NROW 73728
#define NQ 20480
#define OUTN ((size_t)6*2048*6*1024)

// ---------------- scratch ----------------
__device__ __half g_srch [(size_t)NROW*Dm];
__device__ __half g_kvh  [(size_t)NROW*2048];
__device__ __half g_qh   [(size_t)NQ*Dm];
__device__ __half g_ctxh [(size_t)NQ*Dm];
__device__ __half g_a1inh[(size_t)Bb*5120];
__device__ __half g_a2inh[(size_t)Bb*5120];
__device__ float  g_aggv [(size_t)Bb*Dm];
__device__ float  g_nagg [(size_t)Bb*Dm];
__device__ __half g_h1h  [(size_t)Bb*5*Dm];
__device__ __half g_r1h  [(size_t)Bb*5*DFF];
__device__ float  g_f1   [(size_t)Bb*5*Dm];
__device__ __half g_s1h  [(size_t)Bb*Dm];
__device__ __half g_r2h  [(size_t)Bb*DFF];
__device__ float  g_f2   [(size_t)Bb*Dm];
__device__ __half g_wh   [(size_t)31457280];
#define WIN  0
#define WOUT 3145728
#define A1W  4194304
#define A2W  9437184
#define F1W1 14680064
#define F1W2 18874368
#define F2W1 23068672
#define F2W2 27262976

__device__ __forceinline__ uint32_t smem_u32(const void* p) {
    uint32_t a;
    asm("{ .reg .u64 t; cvta.to.shared.u64 t, %1; cvt.u32.u64 %0, t; }" : "=r"(a) : "l"(p));
    return a;
}
__device__ __forceinline__ void cp16(uint32_t dst, const __half* src) {
    asm volatile("cp.async.cg.shared.global [%0], [%1], 16;"
                 :: "r"(dst), "l"(__cvta_generic_to_global(src)) : "memory");
}
#define CP_COMMIT() asm volatile("cp.async.commit_group;" ::: "memory")
#define CP_WAIT(n)  asm volatile("cp.async.wait_group %0;" :: "n"(n) : "memory")

__device__ __forceinline__ __half* scat_ptr(__half* a1, __half* a2, int i, int c) {
    if (i < 10240) return a1 + (long)(i & 2047)*5120 + (i >> 11)*1024 + c;
    int j = i - 10240;
    return a2 + (long)(j & 2047)*5120 + (j >> 11)*1024 + c;
}

// ---------------- f16 mma.sync GEMM, z-batched, opt gather / scatter ----------------
// CTA tile 128x128, BK=64, 256 thr (8 warps 2x4), warp tile 64x32.
// 3-stage cp.async, one barrier per K-step, rows padded to 144B. 2 CTA/SM.
#define SMB 110592
template<int EPI, int OUT16, int GATHER, int SCAT>
__global__ void __launch_bounds__(256, 2) hgemm(
    int K,
    int N0, int M0, const __half* A0, const __half* W0, const float* b0, void* C0,
    int N1, int M1, const __half* A1, const __half* W1, const float* b1, void* C1,
    __half* sc1, __half* sc2)
{
    const __half* A; const __half* W; const float* bias; void* Cv; int M, N;
    const int z = blockIdx.z;
    if (z == 0) { A = A0; W = W0; bias = b0; Cv = C0; M = M0; N = N0; }
    else        { A = A1; W = W1; bias = b1; Cv = C1; M = M1; N = N1; }
    const long bm = (long)blockIdx.y * 128;
    const long bn = (long)blockIdx.x * 128;
    if (bm >= (long)M || bn >= (long)N) return;

    extern __shared__ char dsm[];
    const uint32_t base = smem_u32(dsm);
    const int tid = threadIdx.x;
    const int warp = tid >> 5, lane = tid & 31;
    const int wm = warp >> 2, wn = warp & 3;
    const int gr = lane >> 2, tg = lane & 3;

    float acc[4][4][4];
    #pragma unroll
    for (int i = 0; i < 4; i++)
        #pragma unroll
        for (int j = 0; j < 4; j++) {
            acc[i][j][0] = 0.f; acc[i][j][1] = 0.f;
            acc[i][j][2] = 0.f; acc[i][j][3] = 0.f;
        }

    const int S = K >> 6;
    auto stage = [&](int s, int b) {
        const int k0 = s << 6;
        #pragma unroll
        for (int i = 0; i < 4; i++) {
            int ch = tid + (i << 8);
            int r = ch >> 3, c = ch & 7;
            long rs;
            if (GATHER) {
                int gi = (int)bm + r;
                if (gi < 10240) { int sp = gi >> 11, b2 = gi & 2047; rs = ((long)(sp+1)*2048 + b2)*6; }
                else            { int j = gi - 10240; rs = (long)(j & 2047)*6 + (j >> 11) + 1; }
            } else rs = bm + r;
            cp16(base + (uint32_t)(b*36864 + r*144 + c*16),
                 A + rs*(long)K + k0 + c*8);
            cp16(base + (uint32_t)(b*36864 + 18432 + r*144 + c*16),
                 W + (bn + r)*(long)K + k0 + c*8);
        }
    };

    stage(0, 0); CP_COMMIT();
    stage(1, 1); CP_COMMIT();

    for (int s = 0; s < S; s++) {
        if (s + 1 < S) { CP_WAIT(1); } else { CP_WAIT(0); }
        __syncthreads();
        if (s + 2 < S) { stage(s + 2, (s + 2) % 3); CP_COMMIT(); }
        const uint32_t ab = base + (uint32_t)((s % 3) * 36864);
        const uint32_t bb = ab + 18432u;

        #pragma unroll
        for (int ks = 0; ks < 4; ks++) {
            uint32_t af[4][4], bf[4][2];
            #pragma unroll
            for (int mt = 0; mt < 4; mt++) {
                int row = wm*64 + mt*16 + (lane & 15);
                uint32_t p = ab + (uint32_t)(row*144 + (ks*2 + (lane >> 4))*16);
                asm volatile("ldmatrix.sync.aligned.m8n8.x4.shared.b16 {%0,%1,%2,%3}, [%4];"
                    : "=r"(af[mt][0]), "=r"(af[mt][1]), "=r"(af[mt][2]), "=r"(af[mt][3])
                    : "r"(p));
            }
            #pragma unroll
            for (int np = 0; np < 2; np++) {
                int q = lane >> 3;
                int nrow = wn*32 + np*16 + (q >> 1)*8 + (lane & 7);
                uint32_t p = bb + (uint32_t)(nrow*144 + (ks*2 + (q & 1))*16);
                asm volatile("ldmatrix.sync.aligned.m8n8.x4.shared.b16 {%0,%1,%2,%3}, [%4];"
                    : "=r"(bf[2*np][0]), "=r"(bf[2*np][1]),
                      "=r"(bf[2*np+1][0]), "=r"(bf[2*np+1][1])
                    : "r"(p));
            }
            #pragma unroll
            for (int mt = 0; mt < 4; mt++)
                #pragma unroll
                for (int nt = 0; nt < 4; nt++) {
                    asm volatile(
                        "mma.sync.aligned.m16n8k16.row.col.f32.f16.f16.f32 "
                        "{%0,%1,%2,%3}, {%4,%5,%6,%7}, {%8,%9}, {%0,%1,%2,%3};"
                        : "+f"(acc[mt][nt][0]), "+f"(acc[mt][nt][1]),
                          "+f"(acc[mt][nt][2]), "+f"(acc[mt][nt][3])
                        : "r"(af[mt][0]), "r"(af[mt][1]), "r"(af[mt][2]), "r"(af[mt][3]),
                          "r"(bf[nt][0]), "r"(bf[nt][1]));
                }
        }
    }

    // epilogue
    #pragma unroll
    for (int mt = 0; mt < 4; mt++) {
        long row0 = bm + wm*64 + mt*16 + gr;
        #pragma unroll
        for (int nt = 0; nt < 4; nt++) {
            int col0 = (int)bn + wn*32 + nt*8 + tg*2;
            float bv0 = __ldg(bias + col0);
            float bv1 = __ldg(bias + col0 + 1);
            float v00 = acc[mt][nt][0] + bv0;
            float v01 = acc[mt][nt][1] + bv1;
            float v10 = acc[mt][nt][2] + bv0;
            float v11 = acc[mt][nt][3] + bv1;
            if (EPI == 1) {
                v00 = fmaxf(v00, 0.f); v01 = fmaxf(v01, 0.f);
                v10 = fmaxf(v10, 0.f); v11 = fmaxf(v11, 0.f);
            }
            if (EPI == 2) {
                v00 = 1.f/(1.f+__expf(-v00)); v01 = 1.f/(1.f+__expf(-v01));
                v10 = 1.f/(1.f+__expf(-v10)); v11 = 1.f/(1.f+__expf(-v11));
            }
            if (SCAT) {
                *(__half2*)scat_ptr(sc1, sc2, (int)row0,     col0) = __floats2half2_rn(v00, v01);
                *(__half2*)scat_ptr(sc1, sc2, (int)row0 + 8, col0) = __floats2half2_rn(v10, v11);
            } else if (OUT16) {
                __half* C = (__half*)Cv;
                *(__half2*)(C + row0*(long)N + col0)     = __floats2half2_rn(v00, v01);
                *(__half2*)(C + (row0+8)*(long)N + col0) = __floats2half2_rn(v10, v11);
            } else {
                float* C = (float*)Cv;
                *(float2*)(C + row0*(long)N + col0)     = make_float2(v00, v01);
                *(float2*)(C + (row0+8)*(long)N + col0) = make_float2(v10, v11);
            }
        }
    }
}

// ---------------- merged prep: srcout (blocks 0..36863) + weight cvt ----------------
__global__ void k_prep(const float* __restrict__ F, const float* __restrict__ R,
                       __half* __restrict__ srch, float* __restrict__ out,
                       const float4* s0, const float4* s1, const float4* s2,
                       const float4* s3, const float4* s4, const float4* s5,
                       const float4* s6, const float4* s7, uint2* d) {
    if (blockIdx.x < 36864) {
        long i8 = (long)blockIdx.x * blockDim.x + threadIdx.x;
        long r = i8 >> 7; int d8 = (int)(i8 & 127);
        int l = (int)(r % 6); long sbq = r / 6;
        const float4* F4 = (const float4*)F;
        float4 v0 = F4[i8*2], v1 = F4[i8*2+1];
        if (r >= 12288) {
            ((float4*)out)[i8*2]   = v0;
            ((float4*)out)[i8*2+1] = v1;
        }
        if (l > 0) {
            const float4* R4 = (const float4*)R;
            long rb = (sbq*5 + (l-1))*256 + d8*2;
            float4 e0 = R4[rb], e1 = R4[rb+1];
            v0.x+=e0.x; v0.y+=e0.y; v0.z+=e0.z; v0.w+=e0.w;
            v1.x+=e1.x; v1.y+=e1.y; v1.z+=e1.z; v1.w+=e1.w;
        }
        __half2 h0=__floats2half2_rn(v0.x,v0.y), h1=__floats2half2_rn(v0.z,v0.w);
        __half2 h2=__floats2half2_rn(v1.x,v1.y), h3=__floats2half2_rn(v1.z,v1.w);
        ((uint4*)srch)[i8] = make_uint4(*(uint32_t*)&h0,*(uint32_t*)&h1,*(uint32_t*)&h2,*(uint32_t*)&h3);
    } else {
        long i = (long)(blockIdx.x - 36864) * blockDim.x + threadIdx.x;
        if (i >= 7864320) return;
        const float4* s; long off;
        if      (i <  786432) { s = s0; off = 0; }
        else if (i < 1048576) { s = s1; off =  786432; }
        else if (i < 2359296) { s = s2; off = 1048576; }
        else if (i < 3670016) { s = s3; off = 2359296; }
        else if (i < 4718592) { s = s4; off = 3670016; }
        else if (i < 5767168) { s = s5; off = 4718592; }
        else if (i < 6815744) { s = s6; off = 5767168; }
        else                  { s = s7; off = 6815744; }
        float4 v = s[i - off];
        __half2 a = __floats2half2_rn(v.x, v.y), b = __floats2half2_rn(v.z, v.w);
        d[i] = make_uint2(*(uint32_t*)&a, *(uint32_t*)&b);
    }
}

// ---------------- attention: 2 queries/block, warp = 4 heads, uint4 loads ----------------
__global__ void k_attn(const __half* __restrict__ q, const __half* __restrict__ kv,
                       __half* __restrict__ ctx) {
    const int w = threadIdx.x >> 5, lane = threadIdx.x & 31;
    const int i = blockIdx.x * 2 + (w >> 2);      // query 0..20479
    int seq;
    if (i < 10240) seq = (i/2048 + 1)*2048 + (i & 2047);
    else           seq = (i - 10240) & 2047;
    const __half* kb = kv + (long)seq * 12288;
    const int hb  = (w & 3)*4 + (lane >> 3);      // head 0..15
    const int sub = lane & 7;                     // 8-half slice within head
    const long qoff = (long)i*1024 + hb*64 + sub*8;

    uint4 qv = *(const uint4*)(q + qoff);
    const __half2* qh = (const __half2*)&qv;

    float sc[6];
    #pragma unroll
    for (int j = 0; j < 6; j++) {
        uint4 kvv = *(const uint4*)(kb + j*2048 + hb*64 + sub*8);
        const __half2* kh = (const __half2*)&kvv;
        float p = 0.f;
        #pragma unroll
        for (int t = 0; t < 4; t++) {
            float2 a = __half22float2(qh[t]);
            float2 b = __half22float2(kh[t]);
            p = fmaf(a.x, b.x, p); p = fmaf(a.y, b.y, p);
        }
        p += __shfl_xor_sync(0xffffffffu, p, 1);
        p += __shfl_xor_sync(0xffffffffu, p, 2);
        p += __shfl_xor_sync(0xffffffffu, p, 4);
        sc[j] = p * 0.125f;
    }
    float mx = sc[0];
    #pragma unroll
    for (int j = 1; j < 6; j++) mx = fmaxf(mx, sc[j]);
    float sum = 0.f;
    #pragma unroll
    for (int j = 0; j < 6; j++) { sc[j] = __expf(sc[j]-mx); sum += sc[j]; }
    float inv = 1.f/sum;
    float o[8];
    #pragma unroll
    for (int t = 0; t < 8; t++) o[t] = 0.f;
    #pragma unroll
    for (int j = 0; j < 6; j++) {
        uint4 vv = *(const uint4*)(kb + j*2048 + 1024 + hb*64 + sub*8);
        const __half2* vh = (const __half2*)&vv;
        float wgt = sc[j]*inv;
        #pragma unroll
        for (int t = 0; t < 4; t++) {
            float2 b = __half22float2(vh[t]);
            o[t*2]   = fmaf(wgt, b.x, o[t*2]);
            o[t*2+1] = fmaf(wgt, b.y, o[t*2+1]);
        }
    }
    uint4 ov;
    __half2* oh = (__half2*)&ov;
    #pragma unroll
    for (int t = 0; t < 4; t++) oh[t] = __floats2half2_rn(o[t*2], o[t*2+1]);
    *(uint4*)(ctx + qoff) = ov;
}

// ---------------- LayerNorm ----------------
__device__ __forceinline__ float bsum(float v) {
    __shared__ float sh[9];
    int lane = threadIdx.x & 31, w = threadIdx.x >> 5;
    #pragma unroll
    for (int o = 16; o; o >>= 1) v += __shfl_xor_sync(0xffffffffu, v, o);
    if (lane == 0) sh[w] = v;
    __syncthreads();
    if (w == 0) {
        float r = (lane < 8) ? sh[lane] : 0.f;
        #pragma unroll
        for (int o = 4; o; o >>= 1) r += __shfl_xor_sync(0xffffffffu, r, o);
        if (lane == 0) sh[8] = r;
    }
    __syncthreads();
    float out = sh[8];
    __syncthreads();
    return out;
}
// f32+f32 in, f16 out
__device__ __forceinline__ void ln_row16(const float* pa, const float* pb,
                                         const float* g, const float* bv, __half* ph) {
    int tid = threadIdx.x;
    float v[4];
    #pragma unroll
    for (int t = 0; t < 4; t++) v[t] = pa[tid + t*256] + pb[tid + t*256];
    float mu = bsum(v[0]+v[1]+v[2]+v[3]) * (1.f/1024.f);
    float qv = 0.f;
    #pragma unroll
    for (int t = 0; t < 4; t++) { float d = v[t]-mu; qv += d*d; }
    float r = rsqrtf(bsum(qv) * (1.f/1024.f) + 1e-5f);
    #pragma unroll
    for (int t = 0; t < 4; t++) {
        int idx = tid + t*256;
        ph[idx] = __float2half_rn((v[t]-mu)*r*g[idx] + bv[idx]);
    }
}
// f16+f32 in, f32 out
__device__ __forceinline__ void ln_rowh(const __half* pa, const float* pb,
                                        const float* g, const float* bv, float* po) {
    int tid = threadIdx.x;
    float v[4];
    #pragma unroll
    for (int t = 0; t < 4; t++) v[t] = __half2float(pa[tid + t*256]) + pb[tid + t*256];
    float mu = bsum(v[0]+v[1]+v[2]+v[3]) * (1.f/1024.f);
    float qv = 0.f;
    #pragma unroll
    for (int t = 0; t < 4; t++) { float d = v[t]-mu; qv += d*d; }
    float r = rsqrtf(bsum(qv) * (1.f/1024.f) + 1e-5f);
    #pragma unroll
    for (int t = 0; t < 4; t++) {
        int idx = tid + t*256;
        po[idx] = (v[t]-mu)*r*g[idx] + bv[idx];
    }
}
__global__ void k_ln13(const float* F, const float* aggv, const float* nagg,
                       const float* g1, const float* b1v,
                       const float* g3, const float* b3v,
                       __half* h1h, __half* s1h) {
    int row = blockIdx.x;
    if (row < 10240) {
        int b = row/5, m = row%5;
        ln_row16(F + ((long)b*6+1+m)*1024, aggv + (long)b*1024, g1, b1v,
                 h1h + (long)row*1024);
    } else {
        int b = row - 10240;
        ln_row16(F + (long)b*6144, nagg + (long)b*1024, g3, b3v,
                 s1h + (long)b*1024);
    }
}
__global__ void k_ln24(const __half* h1h, const float* f1, const __half* s1h, const float* f2,
                       const float* g2, const float* b2v,
                       const float* g4, const float* b4v, float* out) {
    int row = blockIdx.x;
    if (row < 10240) {
        int b = row/5, m = row%5;
        ln_rowh(h1h + (long)row*1024, f1 + (long)row*1024, g2, b2v,
                out + ((long)b*6+1+m)*1024);
    } else {
        int b = row - 10240;
        ln_rowh(s1h + (long)b*1024, f2 + (long)b*1024, g4, b4v,
                out + (long)b*6144);
    }
}

// ---------------- host ----------------
template<typename T> static T* sym(const void* s) {
    void* p = nullptr; cudaGetSymbolAddress(&p, s); return (T*)p;
}

extern "C" void kernel_launch(void* const* d_in, const int* in_sizes, int n_in,
                              void* d_out, int out_size) {
    (void)in_sizes; (void)n_in; (void)out_size;
    const float *F=(const float*)d_in[0], *R=(const float*)d_in[1];
    const float *w_in=(const float*)d_in[2], *b_in=(const float*)d_in[3];
    const float *w_out=(const float*)d_in[4], *b_out=(const float*)d_in[5];
    const float *ln1g=(const float*)d_in[6], *ln1b=(const float*)d_in[7];
    const float *ln2g=(const float*)d_in[8], *ln2b=(const float*)d_in[9];
    const float *ln3g=(const float*)d_in[10], *ln3b=(const float*)d_in[11];
    const float *ln4g=(const float*)d_in[12], *ln4b=(const float*)d_in[13];
    const float *f1w1=(const float*)d_in[14], *f1b1=(const float*)d_in[15];
    const float *f1w2=(const float*)d_in[16], *f1b2=(const float*)d_in[17];
    const float *f2w1=(const float*)d_in[18], *f2b1=(const float*)d_in[19];
    const float *f2w2=(const float*)d_in[20], *f2b2=(const float*)d_in[21];
    const float *a1w=(const float*)d_in[22], *a1b=(const float*)d_in[23];
    const float *a2w=(const float*)d_in[24], *a2b=(const float*)d_in[25];
    float* out = (float*)d_out;

    __half *srch=sym<__half>(g_srch), *kvh=sym<__half>(g_kvh);
    __half *qh=sym<__half>(g_qh), *ctxh=sym<__half>(g_ctxh);
    __half *a1inh=sym<__half>(g_a1inh), *a2inh=sym<__half>(g_a2inh);
    float *aggv=sym<float>(g_aggv), *nagg=sym<float>(g_nagg);
    float *f1=sym<float>(g_f1), *f2=sym<float>(g_f2);
    __half *h1h=sym<__half>(g_h1h), *r1h=sym<__half>(g_r1h);
    __half *s1h=sym<__half>(g_s1h), *r2h=sym<__half>(g_r2h);
    __half *wh=sym<__half>(g_wh);

    cudaFuncSetAttribute(hgemm<0,1,0,0>, cudaFuncAttributeMaxDynamicSharedMemorySize, SMB);
    cudaFuncSetAttribute(hgemm<0,1,1,0>, cudaFuncAttributeMaxDynamicSharedMemorySize, SMB);
    cudaFuncSetAttribute(hgemm<0,1,0,1>, cudaFuncAttributeMaxDynamicSharedMemorySize, SMB);
    cudaFuncSetAttribute(hgemm<0,0,0,0>, cudaFuncAttributeMaxDynamicSharedMemorySize, SMB);
    cudaFuncSetAttribute(hgemm<1,1,0,0>, cudaFuncAttributeMaxDynamicSharedMemorySize, SMB);
    cudaFuncSetAttribute(hgemm<2,0,0,0>, cudaFuncAttributeMaxDynamicSharedMemorySize, SMB);

    k_prep<<<67584, 256>>>(F, R, srch, out,
        (const float4*)w_in, (const float4*)w_out, (const float4*)a1w, (const float4*)a2w,
        (const float4*)f1w1, (const float4*)f1w2, (const float4*)f2w1, (const float4*)f2w2,
        (uint2*)wh);

    hgemm<0,1,0,0><<<dim3(16, NROW/128, 1), 256, SMB>>>(1024,
        2048, NROW, srch, wh+WIN+(size_t)1024*1024, b_in+1024, kvh,
        2048, NROW, srch, wh+WIN+(size_t)1024*1024, b_in+1024, kvh,
        (__half*)0, (__half*)0);
    hgemm<0,1,1,0><<<dim3(8, NQ/128, 1), 256, SMB>>>(1024,
        1024, NQ, srch, wh+WIN, b_in, qh,
        1024, NQ, srch, wh+WIN, b_in, qh,
        (__half*)0, (__half*)0);

    k_attn<<<NQ/2, 256>>>(qh, kvh, ctxh);

    hgemm<0,1,0,1><<<dim3(8, NQ/128, 1), 256, SMB>>>(1024,
        1024, NQ, ctxh, wh+WOUT, b_out, (void*)0,
        1024, NQ, ctxh, wh+WOUT, b_out, (void*)0,
        a1inh, a2inh);

    hgemm<2,0,0,0><<<dim3(8, Bb/128, 2), 256, SMB>>>(5120,
        1024, Bb, a1inh, wh+A1W, a1b, aggv,
        1024, Bb, a2inh, wh+A2W, a2b, nagg,
        (__half*)0, (__half*)0);

    k_ln13<<<12288, 256>>>(F, aggv, nagg, ln1g, ln1b, ln3g, ln3b, h1h, s1h);

    hgemm<1,1,0,0><<<dim3(32, (Bb*5)/128, 2), 256, SMB>>>(1024,
        DFF, Bb*5, h1h, wh+F1W1, f1b1, r1h,
        DFF, Bb,   s1h, wh+F2W1, f2b1, r2h,
        (__half*)0, (__half*)0);
    hgemm<0,0,0,0><<<dim3(8, (Bb*5)/128, 2), 256, SMB>>>(DFF,
        1024, Bb*5, r1h, wh+F1W2, f1b2, f1,
        1024, Bb,   r2h, wh+F2W2, f2b2, f2,
        (__half*)0, (__half*)0);

    k_ln24<<<12288, 256>>>(h1h, f1, s1h, f2, ln2g, ln2b, ln4g, ln4b, out);
}